// round 10
// baseline (speedup 1.0000x reference)
#include <cuda_runtime.h>
#include <cuda_bf16.h>
#include <cstdint>
#include <cstddef>

// Problem constants
#define BB   512
#define KK   512
#define DIN  1024
#define DOUT 4096
#define C3K  1536          // 3*K
#define NROWS (BB*KK)      // 262144
#define NIT   (C3K/32)     // 48 k32-iterations

// Scratch (static device globals — no allocation)
__device__ float g_stats[6];
__device__ float g_coef[6];        // scale[3], shift[3]
__device__ float g_bias[DOUT];     // sum_c shift_c * rowsum_c(W)
__device__ int   g_cnt;
__device__ __align__(16) __nv_bfloat16 g_Ah[BB * C3K];    // hi(raw y)
__device__ __align__(16) __nv_bfloat16 g_Al[BB * C3K];    // lo(raw y)
__device__ __align__(16) __nv_bfloat16 g_Bh[DOUT * C3K];  // hi(sc_c * W)
__device__ __align__(16) __nv_bfloat16 g_Bl[DOUT * C3K];  // lo(sc_c * W)

// ---------------------------------------------------------------------------
// Kernel A: y = x @ W_emb^T + b, written as bf16 hi/lo split (raw y).
// W_emb in SMEM (12 KB) -> low regs -> high occupancy -> max LDG MLP.
// ---------------------------------------------------------------------------
__global__ __launch_bounds__(256) void k_embed(const float* __restrict__ x,
                                               const float* __restrict__ Wemb,
                                               const float* __restrict__ bemb) {
    __shared__ float sw[3 * DIN];          // 12 KB
    const int tid = threadIdx.x;
    {
        const float4* W4 = (const float4*)Wemb;
        float4* sw4 = (float4*)sw;
        for (int i = tid; i < 768; i += 256) sw4[i] = W4[i];
    }
    if (blockIdx.x == 0 && tid < 6) g_stats[tid] = 0.0f;
    __syncthreads();

    const int lane = tid & 31;
    const float b0 = bemb[0], b1 = bemb[1], b2 = bemb[2];

    int gw = blockIdx.x * 8 + (tid >> 5);
    const int nw = gridDim.x * 8;
    for (int row = gw; row < NROWS; row += nw) {
        const float4* xr = (const float4*)x + (size_t)row * 256;
        float a0 = 0.f, a1 = 0.f, a2 = 0.f;
#pragma unroll
        for (int j = 0; j < 8; j++) {
            float4 xv = xr[j * 32 + lane];
            const int wi = j * 128 + lane * 4;
            float4 w0 = *(const float4*)&sw[wi];
            float4 w1 = *(const float4*)&sw[DIN + wi];
            float4 w2 = *(const float4*)&sw[2 * DIN + wi];
            a0 += xv.x * w0.x + xv.y * w0.y + xv.z * w0.z + xv.w * w0.w;
            a1 += xv.x * w1.x + xv.y * w1.y + xv.z * w1.z + xv.w * w1.w;
            a2 += xv.x * w2.x + xv.y * w2.y + xv.z * w2.z + xv.w * w2.w;
        }
#pragma unroll
        for (int off = 16; off; off >>= 1) {
            a0 += __shfl_xor_sync(0xffffffffu, a0, off);
            a1 += __shfl_xor_sync(0xffffffffu, a1, off);
            a2 += __shfl_xor_sync(0xffffffffu, a2, off);
        }
        if (lane == 0) {
            const int b = row >> 9, k = row & 511;
            const size_t base = (size_t)b * C3K + k;
            const float yv[3] = {a0 + b0, a1 + b1, a2 + b2};
#pragma unroll
            for (int o = 0; o < 3; o++) {
                __nv_bfloat16 h = __float2bfloat16_rn(yv[o]);
                __nv_bfloat16 l = __float2bfloat16_rn(yv[o] - __bfloat162float(h));
                g_Ah[base + o * 512] = h;
                g_Al[base + o * 512] = l;
            }
        }
    }
}

// ---------------------------------------------------------------------------
// k_stats (+fused finalize)
// ---------------------------------------------------------------------------
__global__ __launch_bounds__(256) void k_stats(const float* __restrict__ gamma,
                                               const float* __restrict__ beta) {
    float s[3] = {0.f, 0.f, 0.f};
    float q[3] = {0.f, 0.f, 0.f};
    const int stride = gridDim.x * blockDim.x;
    const uint4* h4 = (const uint4*)g_Ah;
    const uint4* l4 = (const uint4*)g_Al;
    const int n8 = (BB * C3K) / 8;
    for (int i = blockIdx.x * blockDim.x + threadIdx.x; i < n8; i += stride) {
        const int o = (i % 192) >> 6;
        uint4 hv = h4[i], lv = l4[i];
#pragma unroll
        for (int w = 0; w < 4; w++) {
            __nv_bfloat162 hp = *(__nv_bfloat162*)&((&hv.x)[w]);
            __nv_bfloat162 lp = *(__nv_bfloat162*)&((&lv.x)[w]);
            float y0 = __bfloat162float(hp.x) + __bfloat162float(lp.x);
            float y1 = __bfloat162float(hp.y) + __bfloat162float(lp.y);
            s[o] += y0 + y1;
            q[o] += y0 * y0 + y1 * y1;
        }
    }
#pragma unroll
    for (int off = 16; off; off >>= 1) {
#pragma unroll
        for (int o = 0; o < 3; o++) {
            s[o] += __shfl_xor_sync(0xffffffffu, s[o], off);
            q[o] += __shfl_xor_sync(0xffffffffu, q[o], off);
        }
    }
    __shared__ float rs[6];
    __shared__ int is_last;
    if (threadIdx.x < 6) rs[threadIdx.x] = 0.f;
    __syncthreads();
    if ((threadIdx.x & 31) == 0) {
#pragma unroll
        for (int o = 0; o < 3; o++) {
            atomicAdd(&rs[o], s[o]);
            atomicAdd(&rs[3 + o], q[o]);
        }
    }
    __syncthreads();
    if (threadIdx.x < 6) atomicAdd(&g_stats[threadIdx.x], rs[threadIdx.x]);
    if (threadIdx.x == 0) {
        __threadfence();
        int old = atomicAdd(&g_cnt, 1);
        is_last = (old == (int)gridDim.x - 1) ? 1 : 0;
    }
    __syncthreads();
    if (is_last && threadIdx.x == 0) {
        __threadfence();
        const float n = (float)NROWS;
#pragma unroll
        for (int o = 0; o < 3; o++) {
            float sm = atomicAdd(&g_stats[o], 0.0f);
            float sq = atomicAdd(&g_stats[3 + o], 0.0f);
            float mean = sm / n;
            float var  = sq / n - mean * mean;
            float sc   = gamma[o] * rsqrtf(var + 1e-5f);
            g_coef[o]     = sc;
            g_coef[3 + o] = beta[o] - mean * sc;
        }
        g_cnt = 0;
    }
}

// ---------------------------------------------------------------------------
// convB (after stats): Bh/Bl = bf16 split of (sc_c * W); bias per row.
// ---------------------------------------------------------------------------
__global__ __launch_bounds__(256) void k_convB(const float* __restrict__ W) {
    const int lane = threadIdx.x & 31;
    const int row = blockIdx.x * 8 + (threadIdx.x >> 5);
    const float sc[3] = {g_coef[0], g_coef[1], g_coef[2]};
    const float sh[3] = {g_coef[3], g_coef[4], g_coef[5]};

    const float4* wr = (const float4*)(W + (size_t)row * C3K);
    float bias = 0.f;
#pragma unroll
    for (int p = 0; p < 12; p++) {
        const int i = p * 32 + lane;
        const int o = i >> 7;
        float4 v = wr[i];
        bias += sh[o] * (v.x + v.y + v.z + v.w);
        float a[4] = {v.x * sc[o], v.y * sc[o], v.z * sc[o], v.w * sc[o]};
        __nv_bfloat16 h[4], l[4];
#pragma unroll
        for (int j = 0; j < 4; j++) {
            h[j] = __float2bfloat16_rn(a[j]);
            l[j] = __float2bfloat16_rn(a[j] - __bfloat162float(h[j]));
        }
        const size_t e = (size_t)row * C3K + i * 4;
        *(__nv_bfloat162*)&g_Bh[e]     = __nv_bfloat162(h[0], h[1]);
        *(__nv_bfloat162*)&g_Bh[e + 2] = __nv_bfloat162(h[2], h[3]);
        *(__nv_bfloat162*)&g_Bl[e]     = __nv_bfloat162(l[0], l[1]);
        *(__nv_bfloat162*)&g_Bl[e + 2] = __nv_bfloat162(l[2], l[3]);
    }
#pragma unroll
    for (int off = 16; off; off >>= 1)
        bias += __shfl_xor_sync(0xffffffffu, bias, off);
    if (lane == 0) g_bias[row] = bias;
}

// ---------------------------------------------------------------------------
// k_mma: CTA 64(M)x128(N), grid (32,8), 2 CTAs/SM. 8 warps of 32Mx32N.
// K-iter 32, 4-stage cp.async ring, 1 sync/iter. B fragments for BOTH
// j-steps hoisted to iteration top so A-LDSM and MMA overlap.
// ---------------------------------------------------------------------------
#define LDSM_X4(r0, r1, r2, r3, a) \
    asm volatile("ldmatrix.sync.aligned.m8n8.x4.shared.b16 {%0,%1,%2,%3}, [%4];" \
                 : "=r"(r0), "=r"(r1), "=r"(r2), "=r"(r3) : "r"(a))

#define MMA_BF16(d, a, b0r, b1r) \
    asm volatile("mma.sync.aligned.m16n8k16.row.col.f32.bf16.bf16.f32 " \
                 "{%0,%1,%2,%3},{%4,%5,%6,%7},{%8,%9},{%0,%1,%2,%3};" \
                 : "+f"((d)[0]), "+f"((d)[1]), "+f"((d)[2]), "+f"((d)[3]) \
                 : "r"((a)[0]), "r"((a)[1]), "r"((a)[2]), "r"((a)[3]), \
                   "r"(b0r), "r"(b1r))

__device__ __forceinline__ void cpa16(uint32_t dst, const void* src) {
    asm volatile("cp.async.cg.shared.global [%0], [%1], 16;" :: "r"(dst), "l"(src));
}
#define CPA_COMMIT() asm volatile("cp.async.commit_group;" ::: "memory")
#define CPA_WAIT(n)  asm volatile("cp.async.wait_group %0;" :: "n"(n) : "memory")

__device__ __forceinline__ uint32_t tswz(int row, int c) {
    return (uint32_t)(row * 64 + ((c ^ ((row ^ (row >> 2)) & 3)) << 4));
}

#define TILE_A   4096                    // 64 rows x 64 B
#define TILE_BB  8192                    // 128 rows x 64 B
#define STAGE_B  (2 * TILE_A + 2 * TILE_BB)   // 24576
#define SMEM_B   (4 * STAGE_B)                // 98304

__global__ __launch_bounds__(256, 2) void k_mma(float* __restrict__ out) {
    extern __shared__ __align__(128) char smem[];
    const uint32_t sbase = (uint32_t)__cvta_generic_to_shared(smem);

    const int tid = threadIdx.x;
    const int wid = tid >> 5, lane = tid & 31;
    const int warp_m = wid & 1;
    const int warp_n = wid >> 1;
    const int bn = blockIdx.x;
    const int bm = blockIdx.y;

    const int srow = tid >> 2, scn = tid & 3;
    const __nv_bfloat16* gA[2] = {
        g_Ah + (size_t)(bm * 64 + srow) * C3K + scn * 8,
        g_Al + (size_t)(bm * 64 + srow) * C3K + scn * 8};
    const __nv_bfloat16* gB[2] = {
        g_Bh + (size_t)(bn * 128 + srow) * C3K + scn * 8,
        g_Bl + (size_t)(bn * 128 + srow) * C3K + scn * 8};
    const uint32_t soffA  = tswz(srow, scn);
    const uint32_t soffB0 = tswz(srow, scn);
    const uint32_t soffB1 = tswz(srow + 64, scn);
    const size_t bstride64 = (size_t)64 * C3K;

    uint32_t offA[2][2], offB[2][2];
#pragma unroll
    for (int mf = 0; mf < 2; mf++)
#pragma unroll
        for (int j = 0; j < 2; j++)
            offA[mf][j] = tswz(warp_m * 32 + mf * 16 + (lane & 15),
                               2 * j + (lane >> 4));
#pragma unroll
    for (int ng = 0; ng < 2; ng++)
#pragma unroll
        for (int j = 0; j < 2; j++)
            offB[ng][j] = tswz(warp_n * 32 + ng * 16 + ((lane >> 4) << 3) + (lane & 7),
                               2 * j + ((lane >> 3) & 1));

    float acc[2][4][4];
#pragma unroll
    for (int mf = 0; mf < 2; mf++)
#pragma unroll
        for (int nf = 0; nf < 4; nf++)
#pragma unroll
            for (int r = 0; r < 4; r++) acc[mf][nf][r] = 0.f;

    auto issue = [&](int it) {
        const uint32_t st = sbase + (it & 3) * STAGE_B;
        const int koff = it * 32;
        cpa16(st + 0 * TILE_A + soffA, gA[0] + koff);
        cpa16(st + 1 * TILE_A + soffA, gA[1] + koff);
        const uint32_t bbase = st + 2 * TILE_A;
        cpa16(bbase + soffB0,           gB[0] + koff);
        cpa16(bbase + soffB1,           gB[0] + koff + bstride64);
        cpa16(bbase + TILE_BB + soffB0, gB[1] + koff);
        cpa16(bbase + TILE_BB + soffB1, gB[1] + koff + bstride64);
        CPA_COMMIT();
    };

    issue(0); issue(1); issue(2);

    for (int it = 0; it < NIT; it++) {
        const int rem = NIT - 1 - it;
        if (rem >= 2) CPA_WAIT(2);
        else if (rem == 1) CPA_WAIT(1);
        else CPA_WAIT(0);
        __syncthreads();
        if (it + 3 < NIT) issue(it + 3);

        const uint32_t stg = sbase + (it & 3) * STAGE_B;
        const uint32_t bstg = stg + 2 * TILE_A;

        // Hoist ALL B fragment loads (both j-steps): 8 LDSM up front
        uint32_t bh[2][2][4], bl[2][2][4];
#pragma unroll
        for (int j = 0; j < 2; j++) {
#pragma unroll
            for (int ng = 0; ng < 2; ng++) {
                LDSM_X4(bh[j][ng][0], bh[j][ng][1], bh[j][ng][2], bh[j][ng][3],
                        bstg + offB[ng][j]);
                LDSM_X4(bl[j][ng][0], bl[j][ng][1], bl[j][ng][2], bl[j][ng][3],
                        bstg + TILE_BB + offB[ng][j]);
            }
        }
#pragma unroll
        for (int j = 0; j < 2; j++) {
            uint32_t ah[2][4], al[2][4];
#pragma unroll
            for (int mf = 0; mf < 2; mf++) {
                LDSM_X4(ah[mf][0], ah[mf][1], ah[mf][2], ah[mf][3],
                        stg + 0 * TILE_A + offA[mf][j]);
                LDSM_X4(al[mf][0], al[mf][1], al[mf][2], al[mf][3],
                        stg + 1 * TILE_A + offA[mf][j]);
            }
#pragma unroll
            for (int mf = 0; mf < 2; mf++) {
#pragma unroll
                for (int nf = 0; nf < 4; nf++) {
                    const int ng = nf >> 1, hb = (nf & 1) * 2;
                    MMA_BF16(acc[mf][nf], ah[mf], bh[j][ng][hb], bh[j][ng][hb + 1]);
                    MMA_BF16(acc[mf][nf], ah[mf], bl[j][ng][hb], bl[j][ng][hb + 1]);
                    MMA_BF16(acc[mf][nf], al[mf], bh[j][ng][hb], bh[j][ng][hb + 1]);
                }
            }
        }
    }

    // Epilogue (+bias)
    const int mbase = bm * 64 + warp_m * 32 + (lane >> 2);
    const int nbase = bn * 128 + warp_n * 32 + 2 * (lane & 3);
#pragma unroll
    for (int mf = 0; mf < 2; mf++) {
#pragma unroll
        for (int nf = 0; nf < 4; nf++) {
            const int m = mbase + mf * 16;
            const int n = nbase + nf * 8;
            const float bz0 = g_bias[n], bz1 = g_bias[n + 1];
            *(float2*)(out + (size_t)m * DOUT + n) =
                make_float2(acc[mf][nf][0] + bz0, acc[mf][nf][1] + bz1);
            *(float2*)(out + (size_t)(m + 8) * DOUT + n) =
                make_float2(acc[mf][nf][2] + bz0, acc[mf][nf][3] + bz1);
        }
    }
}

// ---------------------------------------------------------------------------
// Launch
// ---------------------------------------------------------------------------
extern "C" void kernel_launch(void* const* d_in, const int* in_sizes, int n_in,
                              void* d_out, int out_size) {
    const float* x     = (const float*)d_in[0];
    const float* Wemb  = (const float*)d_in[1];
    const float* bemb  = (const float*)d_in[2];
    const float* gamma = (const float*)d_in[3];
    const float* beta  = (const float*)d_in[4];
    const float* Wfc2  = (const float*)d_in[5];
    float* out = (float*)d_out;

    static int smem_set = 0;
    if (!smem_set) {
        cudaFuncSetAttribute(k_mma, cudaFuncAttributeMaxDynamicSharedMemorySize, SMEM_B);
        smem_set = 1;
    }

    k_embed<<<1184, 256>>>(x, Wemb, bemb);
    k_stats<<<96, 256>>>(gamma, beta);
    k_convB<<<512, 256>>>(Wfc2);
    k_mma<<<dim3(32, 8), 256, SMEM_B>>>(out);
}

// round 12
// speedup vs baseline: 1.0385x; 1.0385x over previous
#include <cuda_runtime.h>
#include <cuda_bf16.h>
#include <cstdint>
#include <cstddef>

// Problem constants
#define BB   512
#define KK   512
#define DIN  1024
#define DOUT 4096
#define C3K  1536          // 3*K
#define NROWS (BB*KK)      // 262144
#define NIT   (C3K/32)     // 48 k32-iterations

// Scratch (static device globals — no allocation)
__device__ float g_stats[6];
__device__ float g_coef[6];        // scale[3], shift[3]
__device__ float g_bias[DOUT];     // sum_c shift_c * rowsum_c(W)
__device__ int   g_cnt;
__device__ __align__(16) __nv_bfloat16 g_Ah[BB * C3K];    // hi(raw y)
__device__ __align__(16) __nv_bfloat16 g_Al[BB * C3K];    // lo(raw y)
__device__ __align__(16) __nv_bfloat16 g_Bh[DOUT * C3K];  // hi(sc_c * W)
__device__ __align__(16) __nv_bfloat16 g_Bl[DOUT * C3K];  // lo(sc_c * W)

// ---------------------------------------------------------------------------
// Kernel A (R9 measured-best): y = x @ W_emb^T + b, bf16 hi/lo split.
// ---------------------------------------------------------------------------
__global__ __launch_bounds__(256) void k_embed(const float* __restrict__ x,
                                               const float* __restrict__ Wemb,
                                               const float* __restrict__ bemb) {
    const int tid = threadIdx.x;
    if (blockIdx.x == 0 && tid < 6) g_stats[tid] = 0.0f;
    const int lane = tid & 31;

    float4 w0[8], w1[8], w2[8];
    const float4* W4 = (const float4*)Wemb;
#pragma unroll
    for (int j = 0; j < 8; j++) {
        w0[j] = W4[      j * 32 + lane];
        w1[j] = W4[256 + j * 32 + lane];
        w2[j] = W4[512 + j * 32 + lane];
    }
    const float b0 = bemb[0], b1 = bemb[1], b2 = bemb[2];

    int gw = blockIdx.x * 8 + (tid >> 5);
    const int nw = gridDim.x * 8;
    for (int row = gw; row < NROWS; row += nw) {
        const float4* xr = (const float4*)x + (size_t)row * 256;
        float a0 = 0.f, a1 = 0.f, a2 = 0.f;
#pragma unroll
        for (int j = 0; j < 8; j++) {
            float4 xv = xr[j * 32 + lane];
            a0 += xv.x * w0[j].x + xv.y * w0[j].y + xv.z * w0[j].z + xv.w * w0[j].w;
            a1 += xv.x * w1[j].x + xv.y * w1[j].y + xv.z * w1[j].z + xv.w * w1[j].w;
            a2 += xv.x * w2[j].x + xv.y * w2[j].y + xv.z * w2[j].z + xv.w * w2[j].w;
        }
#pragma unroll
        for (int off = 16; off; off >>= 1) {
            a0 += __shfl_xor_sync(0xffffffffu, a0, off);
            a1 += __shfl_xor_sync(0xffffffffu, a1, off);
            a2 += __shfl_xor_sync(0xffffffffu, a2, off);
        }
        if (lane == 0) {
            const int b = row >> 9, k = row & 511;
            const size_t base = (size_t)b * C3K + k;
            const float yv[3] = {a0 + b0, a1 + b1, a2 + b2};
#pragma unroll
            for (int o = 0; o < 3; o++) {
                __nv_bfloat16 h = __float2bfloat16_rn(yv[o]);
                __nv_bfloat16 l = __float2bfloat16_rn(yv[o] - __bfloat162float(h));
                g_Ah[base + o * 512] = h;
                g_Al[base + o * 512] = l;
            }
        }
    }
}

// ---------------------------------------------------------------------------
// k_stats (+fused finalize)
// ---------------------------------------------------------------------------
__global__ __launch_bounds__(256) void k_stats(const float* __restrict__ gamma,
                                               const float* __restrict__ beta) {
    float s[3] = {0.f, 0.f, 0.f};
    float q[3] = {0.f, 0.f, 0.f};
    const int stride = gridDim.x * blockDim.x;
    const uint4* h4 = (const uint4*)g_Ah;
    const uint4* l4 = (const uint4*)g_Al;
    const int n8 = (BB * C3K) / 8;
    for (int i = blockIdx.x * blockDim.x + threadIdx.x; i < n8; i += stride) {
        const int o = (i % 192) >> 6;
        uint4 hv = h4[i], lv = l4[i];
#pragma unroll
        for (int w = 0; w < 4; w++) {
            __nv_bfloat162 hp = *(__nv_bfloat162*)&((&hv.x)[w]);
            __nv_bfloat162 lp = *(__nv_bfloat162*)&((&lv.x)[w]);
            float y0 = __bfloat162float(hp.x) + __bfloat162float(lp.x);
            float y1 = __bfloat162float(hp.y) + __bfloat162float(lp.y);
            s[o] += y0 + y1;
            q[o] += y0 * y0 + y1 * y1;
        }
    }
#pragma unroll
    for (int off = 16; off; off >>= 1) {
#pragma unroll
        for (int o = 0; o < 3; o++) {
            s[o] += __shfl_xor_sync(0xffffffffu, s[o], off);
            q[o] += __shfl_xor_sync(0xffffffffu, q[o], off);
        }
    }
    __shared__ float rs[6];
    __shared__ int is_last;
    if (threadIdx.x < 6) rs[threadIdx.x] = 0.f;
    __syncthreads();
    if ((threadIdx.x & 31) == 0) {
#pragma unroll
        for (int o = 0; o < 3; o++) {
            atomicAdd(&rs[o], s[o]);
            atomicAdd(&rs[3 + o], q[o]);
        }
    }
    __syncthreads();
    if (threadIdx.x < 6) atomicAdd(&g_stats[threadIdx.x], rs[threadIdx.x]);
    if (threadIdx.x == 0) {
        __threadfence();
        int old = atomicAdd(&g_cnt, 1);
        is_last = (old == (int)gridDim.x - 1) ? 1 : 0;
    }
    __syncthreads();
    if (is_last && threadIdx.x == 0) {
        __threadfence();
        const float n = (float)NROWS;
#pragma unroll
        for (int o = 0; o < 3; o++) {
            float sm = atomicAdd(&g_stats[o], 0.0f);
            float sq = atomicAdd(&g_stats[3 + o], 0.0f);
            float mean = sm / n;
            float var  = sq / n - mean * mean;
            float sc   = gamma[o] * rsqrtf(var + 1e-5f);
            g_coef[o]     = sc;
            g_coef[3 + o] = beta[o] - mean * sc;
        }
        g_cnt = 0;
    }
}

// ---------------------------------------------------------------------------
// convB (after stats): Bh/Bl = bf16 split of (sc_c * W); bias per row.
// ---------------------------------------------------------------------------
__global__ __launch_bounds__(256) void k_convB(const float* __restrict__ W) {
    const int lane = threadIdx.x & 31;
    const int row = blockIdx.x * 8 + (threadIdx.x >> 5);
    const float sc[3] = {g_coef[0], g_coef[1], g_coef[2]};
    const float sh[3] = {g_coef[3], g_coef[4], g_coef[5]};

    const float4* wr = (const float4*)(W + (size_t)row * C3K);
    float bias = 0.f;
#pragma unroll
    for (int p = 0; p < 12; p++) {
        const int i = p * 32 + lane;
        const int o = i >> 7;
        float4 v = wr[i];
        bias += sh[o] * (v.x + v.y + v.z + v.w);
        float a[4] = {v.x * sc[o], v.y * sc[o], v.z * sc[o], v.w * sc[o]};
        __nv_bfloat16 h[4], l[4];
#pragma unroll
        for (int j = 0; j < 4; j++) {
            h[j] = __float2bfloat16_rn(a[j]);
            l[j] = __float2bfloat16_rn(a[j] - __bfloat162float(h[j]));
        }
        const size_t e = (size_t)row * C3K + i * 4;
        *(__nv_bfloat162*)&g_Bh[e]     = __nv_bfloat162(h[0], h[1]);
        *(__nv_bfloat162*)&g_Bh[e + 2] = __nv_bfloat162(h[2], h[3]);
        *(__nv_bfloat162*)&g_Bl[e]     = __nv_bfloat162(l[0], l[1]);
        *(__nv_bfloat162*)&g_Bl[e + 2] = __nv_bfloat162(l[2], l[3]);
    }
#pragma unroll
    for (int off = 16; off; off >>= 1)
        bias += __shfl_xor_sync(0xffffffffu, bias, off);
    if (lane == 0) g_bias[row] = bias;
}

// ---------------------------------------------------------------------------
// k_mma: CTA 64(M)x128(N), grid (32,8), 2 CTAs/SM, 8 warps of 32Mx32N.
// 4-stage cp.async ring with MBARRIER producer/consumer (no __syncthreads in
// the main loop).  full[s]: count 256, armed via cp.async.mbarrier.arrive.NOINC
// per thread (R11 bug: the non-noinc form self-cancels -> deadlock).
// empty[s]: count 8, armed by lane0-per-warp after the stage's last LDSM.
// ---------------------------------------------------------------------------
#define LDSM_X4(r0, r1, r2, r3, a) \
    asm volatile("ldmatrix.sync.aligned.m8n8.x4.shared.b16 {%0,%1,%2,%3}, [%4];" \
                 : "=r"(r0), "=r"(r1), "=r"(r2), "=r"(r3) : "r"(a))

#define MMA_BF16(d, a, b0r, b1r) \
    asm volatile("mma.sync.aligned.m16n8k16.row.col.f32.bf16.bf16.f32 " \
                 "{%0,%1,%2,%3},{%4,%5,%6,%7},{%8,%9},{%0,%1,%2,%3};" \
                 : "+f"((d)[0]), "+f"((d)[1]), "+f"((d)[2]), "+f"((d)[3]) \
                 : "r"((a)[0]), "r"((a)[1]), "r"((a)[2]), "r"((a)[3]), \
                   "r"(b0r), "r"(b1r))

__device__ __forceinline__ void cpa16(uint32_t dst, const void* src) {
    asm volatile("cp.async.cg.shared.global [%0], [%1], 16;" :: "r"(dst), "l"(src));
}
#define MBAR_INIT(a, cnt) \
    asm volatile("mbarrier.init.shared.b64 [%0], %1;" :: "r"(a), "r"(cnt) : "memory")
#define MBAR_ARRIVE(a) \
    asm volatile("mbarrier.arrive.shared.b64 _, [%0];" :: "r"(a) : "memory")
#define CPA_MBAR_ARRIVE(a) \
    asm volatile("cp.async.mbarrier.arrive.noinc.shared.b64 [%0];" :: "r"(a) : "memory")
#define MBAR_WAIT(a, ph) do {                                                  \
    uint32_t _d;                                                               \
    asm volatile("{\n\t.reg .pred p;\n\t"                                      \
        "mbarrier.try_wait.parity.acquire.cta.shared::cta.b64 p, [%1], %2;\n\t"\
        "selp.b32 %0,1,0,p;\n\t}" : "=r"(_d) : "r"(a), "r"((uint32_t)(ph)) : "memory"); \
    if (!_d) {                                                                 \
        asm volatile("{\n\t.reg .pred P1;\n"                                   \
            "WL_%=:\n\t"                                                       \
            "mbarrier.try_wait.parity.acquire.cta.shared::cta.b64 P1, [%0], %1, 0x989680;\n\t" \
            "@P1 bra.uni WD_%=;\n\t"                                           \
            "bra.uni WL_%=;\n"                                                 \
            "WD_%=:\n\t}" :: "r"(a), "r"((uint32_t)(ph)) : "memory");          \
    } } while (0)

__device__ __forceinline__ uint32_t tswz(int row, int c) {
    return (uint32_t)(row * 64 + ((c ^ ((row ^ (row >> 2)) & 3)) << 4));
}

#define TILE_A   4096                         // 64 rows x 64 B
#define TILE_BB  8192                         // 128 rows x 64 B
#define STAGE_B  (2 * TILE_A + 2 * TILE_BB)   // 24576
#define RING_B   (4 * STAGE_B)                // 98304
#define SMEM_B   (RING_B + 64)                // + 8 mbarriers

__global__ __launch_bounds__(256, 2) void k_mma(float* __restrict__ out) {
    extern __shared__ __align__(128) char smem[];
    const uint32_t sbase = (uint32_t)__cvta_generic_to_shared(smem);
    const uint32_t fbar0 = sbase + RING_B;        // full[0..3]
    const uint32_t ebar0 = sbase + RING_B + 32;   // empty[0..3]

    const int tid = threadIdx.x;
    const int wid = tid >> 5, lane = tid & 31;
    const int warp_m = wid & 1;
    const int warp_n = wid >> 1;
    const int bn = blockIdx.x;
    const int bm = blockIdx.y;

    if (tid == 0) {
#pragma unroll
        for (int s = 0; s < 4; s++) {
            MBAR_INIT(fbar0 + s * 8, 256);
            MBAR_INIT(ebar0 + s * 8, 8);
        }
    }
    __syncthreads();

    const int srow = tid >> 2, scn = tid & 3;
    const __nv_bfloat16* gA[2] = {
        g_Ah + (size_t)(bm * 64 + srow) * C3K + scn * 8,
        g_Al + (size_t)(bm * 64 + srow) * C3K + scn * 8};
    const __nv_bfloat16* gB[2] = {
        g_Bh + (size_t)(bn * 128 + srow) * C3K + scn * 8,
        g_Bl + (size_t)(bn * 128 + srow) * C3K + scn * 8};
    const uint32_t soffA  = tswz(srow, scn);
    const uint32_t soffB0 = tswz(srow, scn);
    const uint32_t soffB1 = tswz(srow + 64, scn);
    const size_t bstride64 = (size_t)64 * C3K;

    uint32_t offA[2][2], offB[2][2];
#pragma unroll
    for (int mf = 0; mf < 2; mf++)
#pragma unroll
        for (int j = 0; j < 2; j++)
            offA[mf][j] = tswz(warp_m * 32 + mf * 16 + (lane & 15),
                               2 * j + (lane >> 4));
#pragma unroll
    for (int ng = 0; ng < 2; ng++)
#pragma unroll
        for (int j = 0; j < 2; j++)
            offB[ng][j] = tswz(warp_n * 32 + ng * 16 + ((lane >> 4) << 3) + (lane & 7),
                               2 * j + ((lane >> 3) & 1));

    float acc[2][4][4];
#pragma unroll
    for (int mf = 0; mf < 2; mf++)
#pragma unroll
        for (int nf = 0; nf < 4; nf++)
#pragma unroll
            for (int r = 0; r < 4; r++) acc[mf][nf][r] = 0.f;

    // produce(it2): wait empty[s], issue this thread's 6 cp.asyncs, arm full[s]
    auto produce = [&](int it2) {
        const int s2 = it2 & 3;
        const uint32_t pph = ((it2 >> 2) + 1) & 1;   // first round passes
        MBAR_WAIT(ebar0 + s2 * 8, pph);
        const uint32_t st = sbase + s2 * STAGE_B;
        const int koff = it2 * 32;
        cpa16(st + 0 * TILE_A + soffA, gA[0] + koff);
        cpa16(st + 1 * TILE_A + soffA, gA[1] + koff);
        const uint32_t bbase = st + 2 * TILE_A;
        cpa16(bbase + soffB0,           gB[0] + koff);
        cpa16(bbase + soffB1,           gB[0] + koff + bstride64);
        cpa16(bbase + TILE_BB + soffB0, gB[1] + koff);
        cpa16(bbase + TILE_BB + soffB1, gB[1] + koff + bstride64);
        CPA_MBAR_ARRIVE(fbar0 + s2 * 8);
    };

    produce(0); produce(1); produce(2);

    for (int it = 0; it < NIT; it++) {
        const int s = it & 3;
        const uint32_t cph = (it >> 2) & 1;
        MBAR_WAIT(fbar0 + s * 8, cph);

        const uint32_t stg = sbase + s * STAGE_B;
        const uint32_t bstg = stg + 2 * TILE_A;

        // ALL fragment loads for this stage (16 LDSM), then release the stage
        uint32_t ah[2][2][4], al[2][2][4], bh[2][2][4], bl[2][2][4];
#pragma unroll
        for (int j = 0; j < 2; j++) {
#pragma unroll
            for (int mf = 0; mf < 2; mf++) {
                LDSM_X4(ah[j][mf][0], ah[j][mf][1], ah[j][mf][2], ah[j][mf][3],
                        stg + 0 * TILE_A + offA[mf][j]);
                LDSM_X4(al[j][mf][0], al[j][mf][1], al[j][mf][2], al[j][mf][3],
                        stg + 1 * TILE_A + offA[mf][j]);
            }
#pragma unroll
            for (int ng = 0; ng < 2; ng++) {
                LDSM_X4(bh[j][ng][0], bh[j][ng][1], bh[j][ng][2], bh[j][ng][3],
                        bstg + offB[ng][j]);
                LDSM_X4(bl[j][ng][0], bl[j][ng][1], bl[j][ng][2], bl[j][ng][3],
                        bstg + TILE_BB + offB[ng][j]);
            }
        }
        if (lane == 0) MBAR_ARRIVE(ebar0 + s * 8);

        if (it + 3 < NIT) produce(it + 3);   // overlaps the MMA batch below

#pragma unroll
        for (int j = 0; j < 2; j++) {
#pragma unroll
            for (int mf = 0; mf < 2; mf++) {
#pragma unroll
                for (int nf = 0; nf < 4; nf++) {
                    const int ng = nf >> 1, hb = (nf & 1) * 2;
                    MMA_BF16(acc[mf][nf], ah[j][mf], bh[j][ng][hb], bh[j][ng][hb + 1]);
                    MMA_BF16(acc[mf][nf], ah[j][mf], bl[j][ng][hb], bl[j][ng][hb + 1]);
                    MMA_BF16(acc[mf][nf], al[j][mf], bh[j][ng][hb], bh[j][ng][hb + 1]);
                }
            }
        }
    }

    // Epilogue (+bias)
    const int mbase = bm * 64 + warp_m * 32 + (lane >> 2);
    const int nbase = bn * 128 + warp_n * 32 + 2 * (lane & 3);
#pragma unroll
    for (int mf = 0; mf < 2; mf++) {
#pragma unroll
        for (int nf = 0; nf < 4; nf++) {
            const int m = mbase + mf * 16;
            const int n = nbase + nf * 8;
            const float bz0 = g_bias[n], bz1 = g_bias[n + 1];
            *(float2*)(out + (size_t)m * DOUT + n) =
                make_float2(acc[mf][nf][0] + bz0, acc[mf][nf][1] + bz1);
            *(float2*)(out + (size_t)(m + 8) * DOUT + n) =
                make_float2(acc[mf][nf][2] + bz0, acc[mf][nf][3] + bz1);
        }
    }
}

// ---------------------------------------------------------------------------
// Launch
// ---------------------------------------------------------------------------
extern "C" void kernel_launch(void* const* d_in, const int* in_sizes, int n_in,
                              void* d_out, int out_size) {
    const float* x     = (const float*)d_in[0];
    const float* Wemb  = (const float*)d_in[1];
    const float* bemb  = (const float*)d_in[2];
    const float* gamma = (const float*)d_in[3];
    const float* beta  = (const float*)d_in[4];
    const float* Wfc2  = (const float*)d_in[5];
    float* out = (float*)d_out;

    static int smem_set = 0;
    if (!smem_set) {
        cudaFuncSetAttribute(k_mma, cudaFuncAttributeMaxDynamicSharedMemorySize, SMEM_B);
        smem_set = 1;
    }

    k_embed<<<1184, 256>>>(x, Wemb, bemb);
    k_stats<<<96, 256>>>(gamma, beta);
    k_convB<<<512, 256>>>(Wfc2);
    k_mma<<<dim3(32, 8), 256, SMEM_B>>>(out);
}

// round 13
// speedup vs baseline: 1.0610x; 1.0217x over previous
#include <cuda_runtime.h>
#include <cuda_bf16.h>
#include <cstdint>
#include <cstddef>

// Problem constants
#define BB   512
#define KK   512
#define DIN  1024
#define DOUT 4096
#define C3K  1536          // 3*K
#define NROWS (BB*KK)      // 262144
#define NIT   (C3K/32)     // 48 k32-iterations

// Scratch (static device globals — no allocation)
__device__ float g_stats[6];
__device__ float g_coef[6];            // scale[3], shift[3]
__device__ float g_rsum[3 * DOUT];     // per-channel rowsums of W
__device__ int   g_cnt;
__device__ __align__(16) __nv_bfloat16 g_Ah[BB * C3K];    // hi(raw y)
__device__ __align__(16) __nv_bfloat16 g_Al[BB * C3K];    // lo(raw y)
__device__ __align__(16) __nv_bfloat16 g_Bh[DOUT * C3K];  // hi(raw W)
__device__ __align__(16) __nv_bfloat16 g_Bl[DOUT * C3K];  // lo(raw W)

// ---------------------------------------------------------------------------
// Kernel A (R9 measured-best): y = x @ W_emb^T + b, bf16 hi/lo split.
// ---------------------------------------------------------------------------
__global__ __launch_bounds__(256) void k_embed(const float* __restrict__ x,
                                               const float* __restrict__ Wemb,
                                               const float* __restrict__ bemb) {
    const int tid = threadIdx.x;
    if (blockIdx.x == 0 && tid < 6) g_stats[tid] = 0.0f;
    const int lane = tid & 31;

    float4 w0[8], w1[8], w2[8];
    const float4* W4 = (const float4*)Wemb;
#pragma unroll
    for (int j = 0; j < 8; j++) {
        w0[j] = W4[      j * 32 + lane];
        w1[j] = W4[256 + j * 32 + lane];
        w2[j] = W4[512 + j * 32 + lane];
    }
    const float b0 = bemb[0], b1 = bemb[1], b2 = bemb[2];

    int gw = blockIdx.x * 8 + (tid >> 5);
    const int nw = gridDim.x * 8;
    for (int row = gw; row < NROWS; row += nw) {
        const float4* xr = (const float4*)x + (size_t)row * 256;
        float a0 = 0.f, a1 = 0.f, a2 = 0.f;
#pragma unroll
        for (int j = 0; j < 8; j++) {
            float4 xv = xr[j * 32 + lane];
            a0 += xv.x * w0[j].x + xv.y * w0[j].y + xv.z * w0[j].z + xv.w * w0[j].w;
            a1 += xv.x * w1[j].x + xv.y * w1[j].y + xv.z * w1[j].z + xv.w * w1[j].w;
            a2 += xv.x * w2[j].x + xv.y * w2[j].y + xv.z * w2[j].z + xv.w * w2[j].w;
        }
#pragma unroll
        for (int off = 16; off; off >>= 1) {
            a0 += __shfl_xor_sync(0xffffffffu, a0, off);
            a1 += __shfl_xor_sync(0xffffffffu, a1, off);
            a2 += __shfl_xor_sync(0xffffffffu, a2, off);
        }
        if (lane == 0) {
            const int b = row >> 9, k = row & 511;
            const size_t base = (size_t)b * C3K + k;
            const float yv[3] = {a0 + b0, a1 + b1, a2 + b2};
#pragma unroll
            for (int o = 0; o < 3; o++) {
                __nv_bfloat16 h = __float2bfloat16_rn(yv[o]);
                __nv_bfloat16 l = __float2bfloat16_rn(yv[o] - __bfloat162float(h));
                g_Ah[base + o * 512] = h;
                g_Al[base + o * 512] = l;
            }
        }
    }
}

// ---------------------------------------------------------------------------
// k_prep (fused): (1) raw-W bf16 split + per-channel rowsums; (2) BN stats
// over y = Ah + Al; (3) last block finalizes coefs. Grid 512 x 256.
// ---------------------------------------------------------------------------
__global__ __launch_bounds__(256) void k_prep(const float* __restrict__ W,
                                              const float* __restrict__ gamma,
                                              const float* __restrict__ beta) {
    const int tid = threadIdx.x;
    const int lane = tid & 31;

    // ---- part 1: W split (raw) + rowsums; one warp per output row ----
    {
        const int row = blockIdx.x * 8 + (tid >> 5);   // 0..4095
        const float4* wr = (const float4*)(W + (size_t)row * C3K);
        float rsum[3] = {0.f, 0.f, 0.f};
#pragma unroll
        for (int p = 0; p < 12; p++) {
            const int i = p * 32 + lane;
            const int o = i >> 7;
            float4 v = wr[i];
            rsum[o] += v.x + v.y + v.z + v.w;
            float a[4] = {v.x, v.y, v.z, v.w};
            __nv_bfloat16 h[4], l[4];
#pragma unroll
            for (int j = 0; j < 4; j++) {
                h[j] = __float2bfloat16_rn(a[j]);
                l[j] = __float2bfloat16_rn(a[j] - __bfloat162float(h[j]));
            }
            const size_t e = (size_t)row * C3K + i * 4;
            *(__nv_bfloat162*)&g_Bh[e]     = __nv_bfloat162(h[0], h[1]);
            *(__nv_bfloat162*)&g_Bh[e + 2] = __nv_bfloat162(h[2], h[3]);
            *(__nv_bfloat162*)&g_Bl[e]     = __nv_bfloat162(l[0], l[1]);
            *(__nv_bfloat162*)&g_Bl[e + 2] = __nv_bfloat162(l[2], l[3]);
        }
#pragma unroll
        for (int off = 16; off; off >>= 1)
#pragma unroll
            for (int o = 0; o < 3; o++)
                rsum[o] += __shfl_xor_sync(0xffffffffu, rsum[o], off);
        if (lane == 0) {
#pragma unroll
            for (int o = 0; o < 3; o++) g_rsum[o * DOUT + row] = rsum[o];
        }
    }

    // ---- part 2: BN stats over y = Ah + Al ----
    float s[3] = {0.f, 0.f, 0.f};
    float q[3] = {0.f, 0.f, 0.f};
    {
        const int stride = gridDim.x * blockDim.x;       // 131072
        const uint4* h4 = (const uint4*)g_Ah;
        const uint4* l4 = (const uint4*)g_Al;
        const int n8 = (BB * C3K) / 8;                   // 98304
        for (int i = blockIdx.x * blockDim.x + tid; i < n8; i += stride) {
            const int o = (i % 192) >> 6;
            uint4 hv = h4[i], lv = l4[i];
#pragma unroll
            for (int w = 0; w < 4; w++) {
                __nv_bfloat162 hp = *(__nv_bfloat162*)&((&hv.x)[w]);
                __nv_bfloat162 lp = *(__nv_bfloat162*)&((&lv.x)[w]);
                float y0 = __bfloat162float(hp.x) + __bfloat162float(lp.x);
                float y1 = __bfloat162float(hp.y) + __bfloat162float(lp.y);
                s[o] += y0 + y1;
                q[o] += y0 * y0 + y1 * y1;
            }
        }
    }
#pragma unroll
    for (int off = 16; off; off >>= 1) {
#pragma unroll
        for (int o = 0; o < 3; o++) {
            s[o] += __shfl_xor_sync(0xffffffffu, s[o], off);
            q[o] += __shfl_xor_sync(0xffffffffu, q[o], off);
        }
    }
    __shared__ float rs[6];
    __shared__ int is_last;
    if (tid < 6) rs[tid] = 0.f;
    __syncthreads();
    if (lane == 0) {
#pragma unroll
        for (int o = 0; o < 3; o++) {
            atomicAdd(&rs[o], s[o]);
            atomicAdd(&rs[3 + o], q[o]);
        }
    }
    __syncthreads();
    if (tid < 6) atomicAdd(&g_stats[tid], rs[tid]);
    if (tid == 0) {
        __threadfence();
        int old = atomicAdd(&g_cnt, 1);
        is_last = (old == (int)gridDim.x - 1) ? 1 : 0;
    }
    __syncthreads();
    if (is_last && tid == 0) {
        __threadfence();
        const float n = (float)NROWS;
#pragma unroll
        for (int o = 0; o < 3; o++) {
            float sm = atomicAdd(&g_stats[o], 0.0f);
            float sq = atomicAdd(&g_stats[3 + o], 0.0f);
            float mean = sm / n;
            float var  = sq / n - mean * mean;
            float sc   = gamma[o] * rsqrtf(var + 1e-5f);
            g_coef[o]     = sc;
            g_coef[3 + o] = beta[o] - mean * sc;
        }
        g_cnt = 0;
    }
}

// ---------------------------------------------------------------------------
// k_mma: raw-y @ raw-W with per-channel rescale at k boundaries.
//   acc holds P2 + (sc1/sc2)(P1 + (sc0/sc1) P0); out = acc*sc2 + bias,
//   bias[n] = sum_c sh_c * rowsum_c[n].
// CTA 64x128, grid (32,8), 2 CTAs/SM, 4-stage mbarrier cp.async ring.
// ---------------------------------------------------------------------------
#define LDSM_X4(r0, r1, r2, r3, a) \
    asm volatile("ldmatrix.sync.aligned.m8n8.x4.shared.b16 {%0,%1,%2,%3}, [%4];" \
                 : "=r"(r0), "=r"(r1), "=r"(r2), "=r"(r3) : "r"(a))

#define MMA_BF16(d, a, b0r, b1r) \
    asm volatile("mma.sync.aligned.m16n8k16.row.col.f32.bf16.bf16.f32 " \
                 "{%0,%1,%2,%3},{%4,%5,%6,%7},{%8,%9},{%0,%1,%2,%3};" \
                 : "+f"((d)[0]), "+f"((d)[1]), "+f"((d)[2]), "+f"((d)[3]) \
                 : "r"((a)[0]), "r"((a)[1]), "r"((a)[2]), "r"((a)[3]), \
                   "r"(b0r), "r"(b1r))

__device__ __forceinline__ void cpa16(uint32_t dst, const void* src) {
    asm volatile("cp.async.cg.shared.global [%0], [%1], 16;" :: "r"(dst), "l"(src));
}
#define MBAR_INIT(a, cnt) \
    asm volatile("mbarrier.init.shared.b64 [%0], %1;" :: "r"(a), "r"(cnt) : "memory")
#define MBAR_ARRIVE(a) \
    asm volatile("mbarrier.arrive.shared.b64 _, [%0];" :: "r"(a) : "memory")
#define CPA_MBAR_ARRIVE(a) \
    asm volatile("cp.async.mbarrier.arrive.noinc.shared.b64 [%0];" :: "r"(a) : "memory")
#define MBAR_WAIT(a, ph) do {                                                  \
    uint32_t _d;                                                               \
    asm volatile("{\n\t.reg .pred p;\n\t"                                      \
        "mbarrier.try_wait.parity.acquire.cta.shared::cta.b64 p, [%1], %2;\n\t"\
        "selp.b32 %0,1,0,p;\n\t}" : "=r"(_d) : "r"(a), "r"((uint32_t)(ph)) : "memory"); \
    if (!_d) {                                                                 \
        asm volatile("{\n\t.reg .pred P1;\n"                                   \
            "WL_%=:\n\t"                                                       \
            "mbarrier.try_wait.parity.acquire.cta.shared::cta.b64 P1, [%0], %1, 0x989680;\n\t" \
            "@P1 bra.uni WD_%=;\n\t"                                           \
            "bra.uni WL_%=;\n"                                                 \
            "WD_%=:\n\t}" :: "r"(a), "r"((uint32_t)(ph)) : "memory");          \
    } } while (0)

__device__ __forceinline__ uint32_t tswz(int row, int c) {
    return (uint32_t)(row * 64 + ((c ^ ((row ^ (row >> 2)) & 3)) << 4));
}

#define TILE_A   4096                         // 64 rows x 64 B
#define TILE_BB  8192                         // 128 rows x 64 B
#define STAGE_B  (2 * TILE_A + 2 * TILE_BB)   // 24576
#define RING_B   (4 * STAGE_B)                // 98304
#define SMEM_B   (RING_B + 64)

__global__ __launch_bounds__(256, 2) void k_mma(float* __restrict__ out) {
    extern __shared__ __align__(128) char smem[];
    const uint32_t sbase = (uint32_t)__cvta_generic_to_shared(smem);
    const uint32_t fbar0 = sbase + RING_B;
    const uint32_t ebar0 = sbase + RING_B + 32;

    const int tid = threadIdx.x;
    const int wid = tid >> 5, lane = tid & 31;
    const int warp_m = wid & 1;
    const int warp_n = wid >> 1;
    const int bn = blockIdx.x;
    const int bm = blockIdx.y;

    if (tid == 0) {
#pragma unroll
        for (int s = 0; s < 4; s++) {
            MBAR_INIT(fbar0 + s * 8, 256);
            MBAR_INIT(ebar0 + s * 8, 8);
        }
    }
    __syncthreads();

    // BN coefs (written by k_prep)
    const float sc0 = g_coef[0], sc1 = g_coef[1], sc2 = g_coef[2];
    const float sh0 = g_coef[3], sh1 = g_coef[4], sh2 = g_coef[5];
    const float r01 = sc0 / sc1, r12 = sc1 / sc2;

    const int srow = tid >> 2, scn = tid & 3;
    const __nv_bfloat16* gA[2] = {
        g_Ah + (size_t)(bm * 64 + srow) * C3K + scn * 8,
        g_Al + (size_t)(bm * 64 + srow) * C3K + scn * 8};
    const __nv_bfloat16* gB[2] = {
        g_Bh + (size_t)(bn * 128 + srow) * C3K + scn * 8,
        g_Bl + (size_t)(bn * 128 + srow) * C3K + scn * 8};
    const uint32_t soffA  = tswz(srow, scn);
    const uint32_t soffB0 = tswz(srow, scn);
    const uint32_t soffB1 = tswz(srow + 64, scn);
    const size_t bstride64 = (size_t)64 * C3K;

    uint32_t offA[2][2], offB[2][2];
#pragma unroll
    for (int mf = 0; mf < 2; mf++)
#pragma unroll
        for (int j = 0; j < 2; j++)
            offA[mf][j] = tswz(warp_m * 32 + mf * 16 + (lane & 15),
                               2 * j + (lane >> 4));
#pragma unroll
    for (int ng = 0; ng < 2; ng++)
#pragma unroll
        for (int j = 0; j < 2; j++)
            offB[ng][j] = tswz(warp_n * 32 + ng * 16 + ((lane >> 4) << 3) + (lane & 7),
                               2 * j + ((lane >> 3) & 1));

    float acc[2][4][4];
#pragma unroll
    for (int mf = 0; mf < 2; mf++)
#pragma unroll
        for (int nf = 0; nf < 4; nf++)
#pragma unroll
            for (int r = 0; r < 4; r++) acc[mf][nf][r] = 0.f;

    auto produce = [&](int it2) {
        const int s2 = it2 & 3;
        const uint32_t pph = ((it2 >> 2) + 1) & 1;
        MBAR_WAIT(ebar0 + s2 * 8, pph);
        const uint32_t st = sbase + s2 * STAGE_B;
        const int koff = it2 * 32;
        cpa16(st + 0 * TILE_A + soffA, gA[0] + koff);
        cpa16(st + 1 * TILE_A + soffA, gA[1] + koff);
        const uint32_t bbase = st + 2 * TILE_A;
        cpa16(bbase + soffB0,           gB[0] + koff);
        cpa16(bbase + soffB1,           gB[0] + koff + bstride64);
        cpa16(bbase + TILE_BB + soffB0, gB[1] + koff);
        cpa16(bbase + TILE_BB + soffB1, gB[1] + koff + bstride64);
        CPA_MBAR_ARRIVE(fbar0 + s2 * 8);
    };

    produce(0); produce(1); produce(2);

    for (int it = 0; it < NIT; it++) {
        const int s = it & 3;
        const uint32_t cph = (it >> 2) & 1;
        MBAR_WAIT(fbar0 + s * 8, cph);

        // Issue next stage's loads EARLY (its empty[] was released last it)
        if (it + 3 < NIT) produce(it + 3);

        const uint32_t stg = sbase + s * STAGE_B;
        const uint32_t bstg = stg + 2 * TILE_A;

        uint32_t ah[2][2][4], al[2][2][4], bh[2][2][4], bl[2][2][4];
#pragma unroll
        for (int j = 0; j < 2; j++) {
#pragma unroll
            for (int mf = 0; mf < 2; mf++) {
                LDSM_X4(ah[j][mf][0], ah[j][mf][1], ah[j][mf][2], ah[j][mf][3],
                        stg + 0 * TILE_A + offA[mf][j]);
                LDSM_X4(al[j][mf][0], al[j][mf][1], al[j][mf][2], al[j][mf][3],
                        stg + 1 * TILE_A + offA[mf][j]);
            }
#pragma unroll
            for (int ng = 0; ng < 2; ng++) {
                LDSM_X4(bh[j][ng][0], bh[j][ng][1], bh[j][ng][2], bh[j][ng][3],
                        bstg + offB[ng][j]);
                LDSM_X4(bl[j][ng][0], bl[j][ng][1], bl[j][ng][2], bl[j][ng][3],
                        bstg + TILE_BB + offB[ng][j]);
            }
        }
        if (lane == 0) MBAR_ARRIVE(ebar0 + s * 8);

#pragma unroll
        for (int j = 0; j < 2; j++) {
#pragma unroll
            for (int mf = 0; mf < 2; mf++) {
#pragma unroll
                for (int nf = 0; nf < 4; nf++) {
                    const int ng = nf >> 1, hb = (nf & 1) * 2;
                    MMA_BF16(acc[mf][nf], ah[j][mf], bh[j][ng][hb], bh[j][ng][hb + 1]);
                    MMA_BF16(acc[mf][nf], ah[j][mf], bl[j][ng][hb], bl[j][ng][hb + 1]);
                    MMA_BF16(acc[mf][nf], al[j][mf], bh[j][ng][hb], bh[j][ng][hb + 1]);
                }
            }
        }

        // Channel-boundary rescale: after ch0 (it 15) and ch1 (it 31)
        if (it == 15 || it == 31) {
            const float r = (it == 15) ? r01 : r12;
#pragma unroll
            for (int mf = 0; mf < 2; mf++)
#pragma unroll
                for (int nf = 0; nf < 4; nf++)
#pragma unroll
                    for (int q = 0; q < 4; q++) acc[mf][nf][q] *= r;
        }
    }

    // Epilogue: out = acc*sc2 + bias, bias[n] = sh0*rs0 + sh1*rs1 + sh2*rs2
    const int mbase = bm * 64 + warp_m * 32 + (lane >> 2);
    const int nbase = bn * 128 + warp_n * 32 + 2 * (lane & 3);
#pragma unroll
    for (int mf = 0; mf < 2; mf++) {
#pragma unroll
        for (int nf = 0; nf < 4; nf++) {
            const int m = mbase + mf * 16;
            const int n = nbase + nf * 8;
            const float bz0 = sh0 * g_rsum[n] + sh1 * g_rsum[DOUT + n]
                            + sh2 * g_rsum[2 * DOUT + n];
            const float bz1 = sh0 * g_rsum[n + 1] + sh1 * g_rsum[DOUT + n + 1]
                            + sh2 * g_rsum[2 * DOUT + n + 1];
            *(float2*)(out + (size_t)m * DOUT + n) =
                make_float2(acc[mf][nf][0] * sc2 + bz0, acc[mf][nf][1] * sc2 + bz1);
            *(float2*)(out + (size_t)(m + 8) * DOUT + n) =
                make_float2(acc[mf][nf][2] * sc2 + bz0, acc[mf][nf][3] * sc2 + bz1);
        }
    }
}

// ---------------------------------------------------------------------------
// Launch
// ---------------------------------------------------------------------------
extern "C" void kernel_launch(void* const* d_in, const int* in_sizes, int n_in,
                              void* d_out, int out_size) {
    const float* x     = (const float*)d_in[0];
    const float* Wemb  = (const float*)d_in[1];
    const float* bemb  = (const float*)d_in[2];
    const float* gamma = (const float*)d_in[3];
    const float* beta  = (const float*)d_in[4];
    const float* Wfc2  = (const float*)d_in[5];
    float* out = (float*)d_out;

    static int smem_set = 0;
    if (!smem_set) {
        cudaFuncSetAttribute(k_mma, cudaFuncAttributeMaxDynamicSharedMemorySize, SMEM_B);
        smem_set = 1;
    }

    k_embed<<<1184, 256>>>(x, Wemb, bemb);
    k_prep<<<512, 256>>>(Wfc2, gamma, beta);
    k_mma<<<dim3(32, 8), 256, SMEM_B>>>(out);
}

// round 15
// speedup vs baseline: 1.1931x; 1.1245x over previous
#include <cuda_runtime.h>
#include <cuda_bf16.h>
#include <cstdint>
#include <cstddef>

// Problem constants
#define BB   512
#define KK   512
#define DIN  1024
#define DOUT 4096
#define C3K  1536          // 3*K
#define NROWS (BB*KK)      // 262144
#define NIT   (C3K/32)     // 48 k32-iterations

#define EMB_BLOCKS 1184
#define SPLIT_BLOCKS 512
#define NWARPS_EMB (EMB_BLOCKS * 8)    // 9472

// Scratch (static device globals — no allocation)
__device__ float g_stats[6];
__device__ float g_coef[6];            // scale[3], shift[3]
__device__ float g_rsum[3 * DOUT];     // per-channel rowsums of W
__device__ int   g_cnt;
__device__ __align__(16) __nv_bfloat16 g_Ah[BB * C3K];    // hi(raw y)
__device__ __align__(16) __nv_bfloat16 g_Al[BB * C3K];    // lo(raw y)
__device__ __align__(16) __nv_bfloat16 g_Bh[DOUT * C3K];  // hi(raw W)
__device__ __align__(16) __nv_bfloat16 g_Bl[DOUT * C3K];  // lo(raw W)

__device__ __forceinline__ void cpa16(uint32_t dst, const void* src) {
    asm volatile("cp.async.cg.shared.global [%0], [%1], 16;" :: "r"(dst), "l"(src));
}
#define CPA_COMMIT() asm volatile("cp.async.commit_group;" ::: "memory")
#define CPA_WAIT(n)  asm volatile("cp.async.wait_group %0;" :: "n"(n) : "memory")

// ---------------------------------------------------------------------------
// k_front (fused): blocks [0,1184): embed with per-warp cp.async row ring
// (3 slots x 4KB per warp, dynamic smem 96KB); blocks [1184,1696): raw-W
// bf16 split + per-channel rowsums.
// ---------------------------------------------------------------------------
__global__ __launch_bounds__(256, 2) void k_front(const float* __restrict__ x,
                                                  const float* __restrict__ Wemb,
                                                  const float* __restrict__ bemb,
                                                  const float* __restrict__ W) {
    extern __shared__ __align__(16) float4 sx[];   // [8 warps][3 slots][256]
    const int tid = threadIdx.x;
    const int wid = tid >> 5, lane = tid & 31;

    if (blockIdx.x >= EMB_BLOCKS) {
        // ---- W split + rowsums: one warp per output row ----
        const int row = (blockIdx.x - EMB_BLOCKS) * 8 + wid;   // 0..4095
        const float4* wr = (const float4*)(W + (size_t)row * C3K);
        float rsum[3] = {0.f, 0.f, 0.f};
#pragma unroll
        for (int p = 0; p < 12; p++) {
            const int i = p * 32 + lane;
            const int o = i >> 7;
            float4 v = wr[i];
            rsum[o] += v.x + v.y + v.z + v.w;
            float a[4] = {v.x, v.y, v.z, v.w};
            __nv_bfloat16 h[4], l[4];
#pragma unroll
            for (int j = 0; j < 4; j++) {
                h[j] = __float2bfloat16_rn(a[j]);
                l[j] = __float2bfloat16_rn(a[j] - __bfloat162float(h[j]));
            }
            const size_t e = (size_t)row * C3K + i * 4;
            *(__nv_bfloat162*)&g_Bh[e]     = __nv_bfloat162(h[0], h[1]);
            *(__nv_bfloat162*)&g_Bh[e + 2] = __nv_bfloat162(h[2], h[3]);
            *(__nv_bfloat162*)&g_Bl[e]     = __nv_bfloat162(l[0], l[1]);
            *(__nv_bfloat162*)&g_Bl[e + 2] = __nv_bfloat162(l[2], l[3]);
        }
#pragma unroll
        for (int off = 16; off; off >>= 1)
#pragma unroll
            for (int o = 0; o < 3; o++)
                rsum[o] += __shfl_xor_sync(0xffffffffu, rsum[o], off);
        if (lane == 0) {
#pragma unroll
            for (int o = 0; o < 3; o++) g_rsum[o * DOUT + row] = rsum[o];
        }
        return;
    }

    // ---- embed path ----
    if (blockIdx.x == 0 && tid < 6) g_stats[tid] = 0.0f;

    float4 w0[8], w1[8], w2[8];
    const float4* W4 = (const float4*)Wemb;
#pragma unroll
    for (int j = 0; j < 8; j++) {
        w0[j] = W4[      j * 32 + lane];
        w1[j] = W4[256 + j * 32 + lane];
        w2[j] = W4[512 + j * 32 + lane];
    }
    const float b0 = bemb[0], b1 = bemb[1], b2 = bemb[2];

    const int gw = blockIdx.x * 8 + wid;                  // 0..9471
    const int nr = (NROWS - 1 - gw) / NWARPS_EMB + 1;     // 27 or 28
    // warp's ring base: 3 slots x 256 float4
    float4* ring = sx + (size_t)wid * 3 * 256;
    const uint32_t sb = (uint32_t)__cvta_generic_to_shared(ring);

    // issue row i into slot i%3: lane copies chunks lane+32c, c=0..7 (128B)
    auto issue = [&](int i) {
        const char* src = (const char*)x
            + ((size_t)gw + (size_t)i * NWARPS_EMB) * 4096 + lane * 16;
        const uint32_t dst = sb + (uint32_t)(i % 3) * 4096 + lane * 16;
#pragma unroll
        for (int c = 0; c < 8; c++)
            cpa16(dst + c * 512, src + c * 512);
        CPA_COMMIT();
    };

    issue(0);
    if (nr > 1) issue(1);

    for (int i = 0; i < nr; i++) {
        if (i + 1 < nr) CPA_WAIT(1);   // row i complete
        else CPA_WAIT(0);
        if (i + 2 < nr) issue(i + 2);  // slot (i+2)%3: disjoint from i, i+1

        const float4* xs = ring + (i % 3) * 256;
        float a0 = 0.f, a1 = 0.f, a2 = 0.f;
#pragma unroll
        for (int j = 0; j < 8; j++) {
            float4 xv = xs[j * 32 + lane];
            a0 += xv.x * w0[j].x + xv.y * w0[j].y + xv.z * w0[j].z + xv.w * w0[j].w;
            a1 += xv.x * w1[j].x + xv.y * w1[j].y + xv.z * w1[j].z + xv.w * w1[j].w;
            a2 += xv.x * w2[j].x + xv.y * w2[j].y + xv.z * w2[j].z + xv.w * w2[j].w;
        }
#pragma unroll
        for (int off = 16; off; off >>= 1) {
            a0 += __shfl_xor_sync(0xffffffffu, a0, off);
            a1 += __shfl_xor_sync(0xffffffffu, a1, off);
            a2 += __shfl_xor_sync(0xffffffffu, a2, off);
        }
        if (lane == 0) {
            const int row = gw + i * NWARPS_EMB;
            const int b = row >> 9, k = row & 511;
            const size_t base = (size_t)b * C3K + k;
            const float yv[3] = {a0 + b0, a1 + b1, a2 + b2};
#pragma unroll
            for (int o = 0; o < 3; o++) {
                __nv_bfloat16 h = __float2bfloat16_rn(yv[o]);
                __nv_bfloat16 l = __float2bfloat16_rn(yv[o] - __bfloat162float(h));
                g_Ah[base + o * 512] = h;
                g_Al[base + o * 512] = l;
            }
        }
    }
}
#define FRONT_SMEM (8 * 3 * 4096)    // 98304

// ---------------------------------------------------------------------------
// k_stats: BN stats over y = Ah + Al; last block finalizes coefs.
// ---------------------------------------------------------------------------
__global__ __launch_bounds__(256) void k_stats(const float* __restrict__ gamma,
                                               const float* __restrict__ beta) {
    const int tid = threadIdx.x;
    const int lane = tid & 31;
    float s[3] = {0.f, 0.f, 0.f};
    float q[3] = {0.f, 0.f, 0.f};
    const int stride = gridDim.x * blockDim.x;
    const uint4* h4 = (const uint4*)g_Ah;
    const uint4* l4 = (const uint4*)g_Al;
    const int n8 = (BB * C3K) / 8;
    for (int i = blockIdx.x * blockDim.x + tid; i < n8; i += stride) {
        const int o = (i % 192) >> 6;
        uint4 hv = h4[i], lv = l4[i];
#pragma unroll
        for (int w = 0; w < 4; w++) {
            __nv_bfloat162 hp = *(__nv_bfloat162*)&((&hv.x)[w]);
            __nv_bfloat162 lp = *(__nv_bfloat162*)&((&lv.x)[w]);
            float y0 = __bfloat162float(hp.x) + __bfloat162float(lp.x);
            float y1 = __bfloat162float(hp.y) + __bfloat162float(lp.y);
            s[o] += y0 + y1;
            q[o] += y0 * y0 + y1 * y1;
        }
    }
#pragma unroll
    for (int off = 16; off; off >>= 1) {
#pragma unroll
        for (int o = 0; o < 3; o++) {
            s[o] += __shfl_xor_sync(0xffffffffu, s[o], off);
            q[o] += __shfl_xor_sync(0xffffffffu, q[o], off);
        }
    }
    __shared__ float rs[6];
    __shared__ int is_last;
    if (tid < 6) rs[tid] = 0.f;
    __syncthreads();
    if (lane == 0) {
#pragma unroll
        for (int o = 0; o < 3; o++) {
            atomicAdd(&rs[o], s[o]);
            atomicAdd(&rs[3 + o], q[o]);
        }
    }
    __syncthreads();
    if (tid < 6) atomicAdd(&g_stats[tid], rs[tid]);
    if (tid == 0) {
        __threadfence();
        int old = atomicAdd(&g_cnt, 1);
        is_last = (old == (int)gridDim.x - 1) ? 1 : 0;
    }
    __syncthreads();
    if (is_last && tid == 0) {
        __threadfence();
        const float n = (float)NROWS;
#pragma unroll
        for (int o = 0; o < 3; o++) {
            float sm = atomicAdd(&g_stats[o], 0.0f);
            float sq = atomicAdd(&g_stats[3 + o], 0.0f);
            float mean = sm / n;
            float var  = sq / n - mean * mean;
            float sc   = gamma[o] * rsqrtf(var + 1e-5f);
            g_coef[o]     = sc;
            g_coef[3 + o] = beta[o] - mean * sc;
        }
        g_cnt = 0;
    }
}

// ---------------------------------------------------------------------------
// k_mma: raw-y @ raw-W with per-channel rescale at k boundaries (R13 design).
// CTA 64x128, grid (32,8), 2 CTAs/SM, 4-stage mbarrier cp.async ring.
// ---------------------------------------------------------------------------
#define LDSM_X4(r0, r1, r2, r3, a) \
    asm volatile("ldmatrix.sync.aligned.m8n8.x4.shared.b16 {%0,%1,%2,%3}, [%4];" \
                 : "=r"(r0), "=r"(r1), "=r"(r2), "=r"(r3) : "r"(a))

#define MMA_BF16(d, a, b0r, b1r) \
    asm volatile("mma.sync.aligned.m16n8k16.row.col.f32.bf16.bf16.f32 " \
                 "{%0,%1,%2,%3},{%4,%5,%6,%7},{%8,%9},{%0,%1,%2,%3};" \
                 : "+f"((d)[0]), "+f"((d)[1]), "+f"((d)[2]), "+f"((d)[3]) \
                 : "r"((a)[0]), "r"((a)[1]), "r"((a)[2]), "r"((a)[3]), \
                   "r"(b0r), "r"(b1r))

#define MBAR_INIT(a, cnt) \
    asm volatile("mbarrier.init.shared.b64 [%0], %1;" :: "r"(a), "r"(cnt) : "memory")
#define MBAR_ARRIVE(a) \
    asm volatile("mbarrier.arrive.shared.b64 _, [%0];" :: "r"(a) : "memory")
#define CPA_MBAR_ARRIVE(a) \
    asm volatile("cp.async.mbarrier.arrive.noinc.shared.b64 [%0];" :: "r"(a) : "memory")
#define MBAR_WAIT(a, ph) do {                                                  \
    uint32_t _d;                                                               \
    asm volatile("{\n\t.reg .pred p;\n\t"                                      \
        "mbarrier.try_wait.parity.acquire.cta.shared::cta.b64 p, [%1], %2;\n\t"\
        "selp.b32 %0,1,0,p;\n\t}" : "=r"(_d) : "r"(a), "r"((uint32_t)(ph)) : "memory"); \
    if (!_d) {                                                                 \
        asm volatile("{\n\t.reg .pred P1;\n"                                   \
            "WL_%=:\n\t"                                                       \
            "mbarrier.try_wait.parity.acquire.cta.shared::cta.b64 P1, [%0], %1, 0x989680;\n\t" \
            "@P1 bra.uni WD_%=;\n\t"                                           \
            "bra.uni WL_%=;\n"                                                 \
            "WD_%=:\n\t}" :: "r"(a), "r"((uint32_t)(ph)) : "memory");          \
    } } while (0)

__device__ __forceinline__ uint32_t tswz(int row, int c) {
    return (uint32_t)(row * 64 + ((c ^ ((row ^ (row >> 2)) & 3)) << 4));
}

#define TILE_A   4096
#define TILE_BB  8192
#define STAGE_B  (2 * TILE_A + 2 * TILE_BB)   // 24576
#define RING_B   (4 * STAGE_B)                // 98304
#define SMEM_B   (RING_B + 64)

__global__ __launch_bounds__(256, 2) void k_mma(float* __restrict__ out) {
    extern __shared__ __align__(128) char smem[];
    const uint32_t sbase = (uint32_t)__cvta_generic_to_shared(smem);
    const uint32_t fbar0 = sbase + RING_B;
    const uint32_t ebar0 = sbase + RING_B + 32;

    const int tid = threadIdx.x;
    const int wid = tid >> 5, lane = tid & 31;
    const int warp_m = wid & 1;
    const int warp_n = wid >> 1;
    const int bn = blockIdx.x;
    const int bm = blockIdx.y;

    if (tid == 0) {
#pragma unroll
        for (int s = 0; s < 4; s++) {
            MBAR_INIT(fbar0 + s * 8, 256);
            MBAR_INIT(ebar0 + s * 8, 8);
        }
    }
    __syncthreads();

    const float sc0 = g_coef[0], sc1 = g_coef[1], sc2 = g_coef[2];
    const float sh0 = g_coef[3], sh1 = g_coef[4], sh2 = g_coef[5];
    const float r01 = sc0 / sc1, r12 = sc1 / sc2;

    const int srow = tid >> 2, scn = tid & 3;
    const __nv_bfloat16* gA[2] = {
        g_Ah + (size_t)(bm * 64 + srow) * C3K + scn * 8,
        g_Al + (size_t)(bm * 64 + srow) * C3K + scn * 8};
    const __nv_bfloat16* gB[2] = {
        g_Bh + (size_t)(bn * 128 + srow) * C3K + scn * 8,
        g_Bl + (size_t)(bn * 128 + srow) * C3K + scn * 8};
    const uint32_t soffA  = tswz(srow, scn);
    const uint32_t soffB0 = tswz(srow, scn);
    const uint32_t soffB1 = tswz(srow + 64, scn);
    const size_t bstride64 = (size_t)64 * C3K;

    uint32_t offA[2][2], offB[2][2];
#pragma unroll
    for (int mf = 0; mf < 2; mf++)
#pragma unroll
        for (int j = 0; j < 2; j++)
            offA[mf][j] = tswz(warp_m * 32 + mf * 16 + (lane & 15),
                               2 * j + (lane >> 4));
#pragma unroll
    for (int ng = 0; ng < 2; ng++)
#pragma unroll
        for (int j = 0; j < 2; j++)
            offB[ng][j] = tswz(warp_n * 32 + ng * 16 + ((lane >> 4) << 3) + (lane & 7),
                               2 * j + ((lane >> 3) & 1));

    float acc[2][4][4];
#pragma unroll
    for (int mf = 0; mf < 2; mf++)
#pragma unroll
        for (int nf = 0; nf < 4; nf++)
#pragma unroll
            for (int r = 0; r < 4; r++) acc[mf][nf][r] = 0.f;

    auto produce = [&](int it2) {
        const int s2 = it2 & 3;
        const uint32_t pph = ((it2 >> 2) + 1) & 1;
        MBAR_WAIT(ebar0 + s2 * 8, pph);
        const uint32_t st = sbase + s2 * STAGE_B;
        const int koff = it2 * 32;
        cpa16(st + 0 * TILE_A + soffA, gA[0] + koff);
        cpa16(st + 1 * TILE_A + soffA, gA[1] + koff);
        const uint32_t bbase = st + 2 * TILE_A;
        cpa16(bbase + soffB0,           gB[0] + koff);
        cpa16(bbase + soffB1,           gB[0] + koff + bstride64);
        cpa16(bbase + TILE_BB + soffB0, gB[1] + koff);
        cpa16(bbase + TILE_BB + soffB1, gB[1] + koff + bstride64);
        CPA_MBAR_ARRIVE(fbar0 + s2 * 8);
    };

    produce(0); produce(1); produce(2);

    for (int it = 0; it < NIT; it++) {
        const int s = it & 3;
        const uint32_t cph = (it >> 2) & 1;
        MBAR_WAIT(fbar0 + s * 8, cph);
        if (it + 3 < NIT) produce(it + 3);

        const uint32_t stg = sbase + s * STAGE_B;
        const uint32_t bstg = stg + 2 * TILE_A;

        uint32_t ah[2][2][4], al[2][2][4], bh[2][2][4], bl[2][2][4];
#pragma unroll
        for (int j = 0; j < 2; j++) {
#pragma unroll
            for (int mf = 0; mf < 2; mf++) {
                LDSM_X4(ah[j][mf][0], ah[j][mf][1], ah[j][mf][2], ah[j][mf][3],
                        stg + 0 * TILE_A + offA[mf][j]);
                LDSM_X4(al[j][mf][0], al[j][mf][1], al[j][mf][2], al[j][mf][3],
                        stg + 1 * TILE_A + offA[mf][j]);
            }
#pragma unroll
            for (int ng = 0; ng < 2; ng++) {
                LDSM_X4(bh[j][ng][0], bh[j][ng][1], bh[j][ng][2], bh[j][ng][3],
                        bstg + offB[ng][j]);
                LDSM_X4(bl[j][ng][0], bl[j][ng][1], bl[j][ng][2], bl[j][ng][3],
                        bstg + TILE_BB + offB[ng][j]);
            }
        }
        if (lane == 0) MBAR_ARRIVE(ebar0 + s * 8);

#pragma unroll
        for (int j = 0; j < 2; j++) {
#pragma unroll
            for (int mf = 0; mf < 2; mf++) {
#pragma unroll
                for (int nf = 0; nf < 4; nf++) {
                    const int ng = nf >> 1, hb = (nf & 1) * 2;
                    MMA_BF16(acc[mf][nf], ah[j][mf], bh[j][ng][hb], bh[j][ng][hb + 1]);
                    MMA_BF16(acc[mf][nf], ah[j][mf], bl[j][ng][hb], bl[j][ng][hb + 1]);
                    MMA_BF16(acc[mf][nf], al[j][mf], bh[j][ng][hb], bh[j][ng][hb + 1]);
                }
            }
        }

        if (it == 15 || it == 31) {
            const float r = (it == 15) ? r01 : r12;
#pragma unroll
            for (int mf = 0; mf < 2; mf++)
#pragma unroll
                for (int nf = 0; nf < 4; nf++)
#pragma unroll
                    for (int q = 0; q < 4; q++) acc[mf][nf][q] *= r;
        }
    }

    const int mbase = bm * 64 + warp_m * 32 + (lane >> 2);
    const int nbase = bn * 128 + warp_n * 32 + 2 * (lane & 3);
#pragma unroll
    for (int mf = 0; mf < 2; mf++) {
#pragma unroll
        for (int nf = 0; nf < 4; nf++) {
            const int m = mbase + mf * 16;
            const int n = nbase + nf * 8;
            const float bz0 = sh0 * g_rsum[n] + sh1 * g_rsum[DOUT + n]
                            + sh2 * g_rsum[2 * DOUT + n];
            const float bz1 = sh0 * g_rsum[n + 1] + sh1 * g_rsum[DOUT + n + 1]
                            + sh2 * g_rsum[2 * DOUT + n + 1];
            *(float2*)(out + (size_t)m * DOUT + n) =
                make_float2(acc[mf][nf][0] * sc2 + bz0, acc[mf][nf][1] * sc2 + bz1);
            *(float2*)(out + (size_t)(m + 8) * DOUT + n) =
                make_float2(acc[mf][nf][2] * sc2 + bz0, acc[mf][nf][3] * sc2 + bz1);
        }
    }
}

// ---------------------------------------------------------------------------
// Launch
// ---------------------------------------------------------------------------
extern "C" void kernel_launch(void* const* d_in, const int* in_sizes, int n_in,
                              void* d_out, int out_size) {
    const float* x     = (const float*)d_in[0];
    const float* Wemb  = (const float*)d_in[1];
    const float* bemb  = (const float*)d_in[2];
    const float* gamma = (const float*)d_in[3];
    const float* beta  = (const float*)d_in[4];
    const float* Wfc2  = (const float*)d_in[5];
    float* out = (float*)d_out;

    static int smem_set = 0;
    if (!smem_set) {
        cudaFuncSetAttribute(k_mma, cudaFuncAttributeMaxDynamicSharedMemorySize, SMEM_B);
        cudaFuncSetAttribute(k_front, cudaFuncAttributeMaxDynamicSharedMemorySize, FRONT_SMEM);
        smem_set = 1;
    }

    k_front<<<EMB_BLOCKS + SPLIT_BLOCKS, 256, FRONT_SMEM>>>(x, Wemb, bemb, Wfc2);
    k_stats<<<148, 256>>>(gamma, beta);
    k_mma<<<dim3(32, 8), 256, SMEM_B>>>(out);
}